// round 8
// baseline (speedup 1.0000x reference)
#include <cuda_runtime.h>
#include <cuda_fp16.h>
#include <cstdint>

// MaddnessConv2d, round 8: 4 lanes/pixel (784 blocks -> 40 warps/SM),
// upfront gathers, two-tree fp16 accumulation, rotation-conflict-free LDS.
//
//   x:            (16, 64, 56, 56) f32
//   split_idxs:   (16, 4) i32
//   split_vals:   (16, 4, 8) f32
//   lookup_tables:(16, 16, 64) f32
//   bias:         (64,) f32
//   out:          (16, 64, 56, 56) f32
//
// out[p][ch] = sum_cb LUT[cb][e_cb(p)][ch] + bias[ch]. LUT in smem as fp16
// (row (cb,e) = 128B = 8 slots x 8 channels). 4 lanes per pixel: lane `part`
// owns slots s(rr) = part + 4*((rr + (p&1)) & 1), rr in {0,1}; each 8-lane
// LDS phase (2 pixels x 4 parts) covers all 8 bank-groups regardless of the
// data-dependent code e. Two fp16 trees (cb 0-7 / 8-15) merged in fp32.

#define NCB   16
#define HW    3136          // 56*56
#define WID   56
#define TPB   256
#define NBLK  784           // 784*256 == 4*50176 exactly; 64 pixels/block

// smem layout:
//   half  s_lut[16*16*64]    32768 B  (reused as fp32 transpose buf)
//   float s_bias[64]           256 B
//   float s_sval[16*4*8]      2048 B
//   int   s_off[64]            256 B
//   int   s_kpos[64]           256 B
#define SM_LUT   0
#define SM_BIAS  32768
#define SM_SVAL  33024
#define SM_OFF   35072
#define SM_KPOS  35328
#define SMEM_BYTES 35584

__global__ __launch_bounds__(TPB, 5) void maddness_conv2d_kernel(
    const float* __restrict__ x,
    const int*   __restrict__ split_idxs,
    const float* __restrict__ split_vals,
    const float* __restrict__ lut,
    const float* __restrict__ bias,
    float*       __restrict__ out)
{
    extern __shared__ char smem_raw[];
    char*  s_lutb = smem_raw + SM_LUT;
    float* s_bias = (float*)(smem_raw + SM_BIAS);
    float* s_sval = (float*)(smem_raw + SM_SVAL);
    int*   s_off  = (int*)  (smem_raw + SM_OFF);
    int*   s_kpos = (int*)  (smem_raw + SM_KPOS);

    const int tid = threadIdx.x;

    // --- cooperative smem fill: LUT fp32 -> fp16, 128B rows ---
    {
        const float4* lut4 = (const float4*)lut;   // 4096 float4 (4 ch each)
        #pragma unroll
        for (int i = tid; i < 4096; i += TPB) {
            float4 lv = lut4[i];
            __half2 h0 = __floats2half2_rn(lv.x, lv.y);
            __half2 h1 = __floats2half2_rn(lv.z, lv.w);
            uint2 pk;
            pk.x = *(unsigned*)&h0;
            pk.y = *(unsigned*)&h1;
            *(uint2*)(s_lutb + (i >> 4) * 128 + (i & 15) * 8) = pk;
        }
    }
    if (tid < 64) {
        int cb = tid >> 2;                     // tid = cb*4 + t
        int si = split_idxs[tid];
        int f  = cb * 36 + si;
        int ch = f / 9;
        int r  = f - ch * 9;                   // kernel position 0..8
        int dy = r / 3 - 1;
        int dx = r - (r / 3) * 3 - 1;
        s_off[tid]  = ch * HW + dy * WID + dx;
        s_kpos[tid] = r;
        s_bias[tid] = bias[tid];
    }
    #pragma unroll
    for (int i = tid; i < NCB * 32; i += TPB) s_sval[i] = split_vals[i];
    __syncthreads();

    // --- indices: 4 lanes per pixel ---
    const int gt   = blockIdx.x * TPB + tid;   // exact grid
    const int p    = gt >> 2;                  // pixel
    const int part = gt & 3;
    const int b    = p / HW;
    const int rem  = p - b * HW;
    const int y    = rem / WID;
    const int xw   = rem - y * WID;
    const float* xb = x + (size_t)b * 64 * HW + rem;

    // 3x3 validity bitmask (pad=1)
    unsigned vm = 0;
    #pragma unroll
    for (int ki = 0; ki < 3; ki++)
        #pragma unroll
        for (int kj = 0; kj < 3; kj++) {
            bool ok = ((unsigned)(y + ki - 1) < 56u) & ((unsigned)(xw + kj - 1) < 56u);
            vm |= (ok ? 1u : 0u) << (ki * 3 + kj);
        }

    // --- upfront gathers for my 4 codebooks (values don't depend on e) ---
    float v[4][4];
    #pragma unroll
    for (int c = 0; c < 4; c++)
        #pragma unroll
        for (int t = 0; t < 4; t++) {
            const int idx = (4 * part + c) * 4 + t;
            v[c][t] = ((vm >> s_kpos[idx]) & 1u) ? __ldg(xb + s_off[idx]) : 0.0f;
        }

    // --- threshold walk (pure ALU) ---
    unsigned mine = 0;
    #pragma unroll
    for (int c = 0; c < 4; c++) {
        const int cb = 4 * part + c;
        int e = 0;
        #pragma unroll
        for (int t = 0; t < 4; t++) {
            const float thr = s_sval[cb * 32 + t * 8 + e];
            e = 2 * e + (v[c][t] >= thr ? 1 : 0);
        }
        mine |= (unsigned)e << (4 * c);
    }

    // Merge codes across the 4 lanes of this pixel (lane bits 0-1 = part).
    unsigned long long codes = (unsigned long long)mine << (16 * part);
    codes |= __shfl_xor_sync(0xffffffffu, codes, 1);
    codes |= __shfl_xor_sync(0xffffffffu, codes, 2);

    // --- accumulate: slots s(rr) = part + 4*((rr + rot)&1), two fp16 trees ---
    const int rot = p & 1;
    int soff[2];
    #pragma unroll
    for (int rr = 0; rr < 2; rr++) soff[rr] = (part + 4 * ((rr + rot) & 1)) * 16;

    __half2 accA[2][4], accB[2][4];
    #pragma unroll
    for (int rr = 0; rr < 2; rr++)
        #pragma unroll
        for (int k = 0; k < 4; k++) {
            accA[rr][k] = __half2half2(__ushort_as_half(0));
            accB[rr][k] = __half2half2(__ushort_as_half(0));
        }

    #pragma unroll
    for (int cb = 0; cb < 8; cb++) {
        const int eA = (int)((codes >> (4 * cb)) & 15ull);
        const int eB = (int)((codes >> (4 * (cb + 8))) & 15ull);
        const char* rowA = s_lutb + (cb * 16 + eA) * 128;
        const char* rowB = s_lutb + ((cb + 8) * 16 + eB) * 128;
        #pragma unroll
        for (int rr = 0; rr < 2; rr++) {
            uint4 a = *(const uint4*)(rowA + soff[rr]);
            uint4 bq = *(const uint4*)(rowB + soff[rr]);
            accA[rr][0] = __hadd2(accA[rr][0], *(__half2*)&a.x);
            accA[rr][1] = __hadd2(accA[rr][1], *(__half2*)&a.y);
            accA[rr][2] = __hadd2(accA[rr][2], *(__half2*)&a.z);
            accA[rr][3] = __hadd2(accA[rr][3], *(__half2*)&a.w);
            accB[rr][0] = __hadd2(accB[rr][0], *(__half2*)&bq.x);
            accB[rr][1] = __hadd2(accB[rr][1], *(__half2*)&bq.y);
            accB[rr][2] = __hadd2(accB[rr][2], *(__half2*)&bq.z);
            accB[rr][3] = __hadd2(accB[rr][3], *(__half2*)&bq.w);
        }
    }

    // --- fp32 merge + transpose via smem (reuse dead LUT region) ---
    __syncthreads();
    float4* s_buf = (float4*)smem_raw;   // granule (g*129 + px*2 + h), g<8, px<64
    const int pxl = tid >> 2;            // local pixel 0..63
    #pragma unroll
    for (int rr = 0; rr < 2; rr++) {
        const int g = soff[rr] >> 4;     // channel-8 group 0..7
        float2 fA0 = __half22float2(accA[rr][0]), fB0 = __half22float2(accB[rr][0]);
        float2 fA1 = __half22float2(accA[rr][1]), fB1 = __half22float2(accB[rr][1]);
        float2 fA2 = __half22float2(accA[rr][2]), fB2 = __half22float2(accB[rr][2]);
        float2 fA3 = __half22float2(accA[rr][3]), fB3 = __half22float2(accB[rr][3]);
        float4 lo = make_float4(fA0.x + fB0.x, fA0.y + fB0.y,
                                fA1.x + fB1.x, fA1.y + fB1.y);
        float4 hi = make_float4(fA2.x + fB2.x, fA2.y + fB2.y,
                                fA3.x + fB3.x, fA3.y + fB3.y);
        s_buf[g * 129 + pxl * 2 + 0] = lo;
        s_buf[g * 129 + pxl * 2 + 1] = hi;
    }
    __syncthreads();

    // --- coalesced stores + bias: thread (gq = tid>>6, px = tid&63)
    //     stores channel groups {2gq, 2gq+1} for local pixel px.
    const int gq = tid >> 6;
    const int px = tid & 63;
    const int pg = blockIdx.x * 64 + px;       // global pixel
    const int bb = pg / HW;
    const int rr2 = pg - bb * HW;
    float* ob = out + (size_t)bb * 64 * HW + rr2;

    #pragma unroll
    for (int j = 0; j < 2; j++) {
        const int g = 2 * gq + j;
        float4 lo = s_buf[g * 129 + px * 2 + 0];
        float4 hi = s_buf[g * 129 + px * 2 + 1];
        const int ch = 8 * g;
        ob[(ch + 0) * HW] = lo.x + s_bias[ch + 0];
        ob[(ch + 1) * HW] = lo.y + s_bias[ch + 1];
        ob[(ch + 2) * HW] = lo.z + s_bias[ch + 2];
        ob[(ch + 3) * HW] = lo.w + s_bias[ch + 3];
        ob[(ch + 4) * HW] = hi.x + s_bias[ch + 4];
        ob[(ch + 5) * HW] = hi.y + s_bias[ch + 5];
        ob[(ch + 6) * HW] = hi.z + s_bias[ch + 6];
        ob[(ch + 7) * HW] = hi.w + s_bias[ch + 7];
    }
}

extern "C" void kernel_launch(void* const* d_in, const int* in_sizes, int n_in,
                              void* d_out, int out_size)
{
    const float* x    = (const float*)d_in[0];
    const int*   sidx = (const int*)  d_in[1];
    const float* sval = (const float*)d_in[2];
    const float* lut  = (const float*)d_in[3];
    const float* bias = (const float*)d_in[4];
    float* out = (float*)d_out;

    cudaFuncSetAttribute(maddness_conv2d_kernel,
                         cudaFuncAttributeMaxDynamicSharedMemorySize,
                         SMEM_BYTES);

    maddness_conv2d_kernel<<<NBLK, TPB, SMEM_BYTES>>>(x, sidx, sval, lut, bias, out);
}

// round 9
// speedup vs baseline: 1.1026x; 1.1026x over previous
#include <cuda_runtime.h>
#include <cuda_fp16.h>
#include <cstdint>

// MaddnessConv2d, round 9: R7 base (2 lanes/pixel, fp16 LUT, rotation-
// conflict-free LDS) + 784-block balance + batched gathers + conflict-free
// sval (stride 33) + two-tree fp16 accumulation with fp32 merge.
//
//   x:            (16, 64, 56, 56) f32
//   split_idxs:   (16, 4) i32
//   split_vals:   (16, 4, 8) f32
//   lookup_tables:(16, 16, 64) f32
//   bias:         (64,) f32
//   out:          (16, 64, 56, 56) f32
//
// out[p][ch] = sum_cb LUT[cb][e_cb(p)][ch] + bias[ch]. LUT in smem as fp16
// (row (cb,e) = 128B = 8 slots x 8 channels). 2 lanes/pixel: lane `part`
// reads slots s(rr) = ((2rr + 2(p&3))&7)|part  -> every 8-lane LDS phase
// (4 px x 2 parts) covers all 8 bank-groups, independent of the code e.

#define NCB   16
#define HW    3136          // 56*56
#define WID   56
#define TPB   128
#define NBLK  784           // 784*128 == 2*50176 exactly; 64 pixels/block

// smem layout:
//   half  s_lut[16*16*64]    32768 B  (reused as fp32 [16][66] float4 buf)
//   float s_bias[64]           256 B
//   float s_sval[16*33]       2112 B  (stride-33: conflict-free walk)
//   int   s_off[64]            256 B
//   int   s_kpos[64]           256 B
#define SM_LUT   0
#define SM_BIAS  32768
#define SM_SVAL  33024
#define SM_OFF   35136
#define SM_KPOS  35392
#define SMEM_BYTES 35648

__global__ __launch_bounds__(TPB, 6) void maddness_conv2d_kernel(
    const float* __restrict__ x,
    const int*   __restrict__ split_idxs,
    const float* __restrict__ split_vals,
    const float* __restrict__ lut,
    const float* __restrict__ bias,
    float*       __restrict__ out)
{
    extern __shared__ char smem_raw[];
    char*  s_lutb = smem_raw + SM_LUT;
    float* s_bias = (float*)(smem_raw + SM_BIAS);
    float* s_sval = (float*)(smem_raw + SM_SVAL);
    int*   s_off  = (int*)  (smem_raw + SM_OFF);
    int*   s_kpos = (int*)  (smem_raw + SM_KPOS);

    const int tid = threadIdx.x;

    // --- cooperative smem fill: LUT fp32 -> fp16, 128B rows ---
    {
        const float4* lut4 = (const float4*)lut;   // 4096 float4 (4 ch each)
        #pragma unroll
        for (int i = tid; i < 4096; i += TPB) {
            float4 lv = lut4[i];
            __half2 h0 = __floats2half2_rn(lv.x, lv.y);
            __half2 h1 = __floats2half2_rn(lv.z, lv.w);
            uint2 pk;
            pk.x = *(unsigned*)&h0;
            pk.y = *(unsigned*)&h1;
            *(uint2*)(s_lutb + (i >> 4) * 128 + (i & 15) * 8) = pk;
        }
    }
    if (tid < 64) {
        int cb = tid >> 2;                     // tid = cb*4 + t
        int si = split_idxs[tid];
        int f  = cb * 36 + si;
        int ch = f / 9;
        int r  = f - ch * 9;                   // kernel position 0..8
        int dy = r / 3 - 1;
        int dx = r - (r / 3) * 3 - 1;
        s_off[tid]  = ch * HW + dy * WID + dx;
        s_kpos[tid] = r;
        s_bias[tid] = bias[tid];
    }
    #pragma unroll
    for (int i = tid; i < NCB * 32; i += TPB)
        s_sval[(i >> 5) * 33 + (i & 31)] = split_vals[i];
    __syncthreads();

    // --- indices: 2 lanes per pixel ---
    const int gt   = blockIdx.x * TPB + tid;   // exact grid
    const int p    = gt >> 1;                  // pixel
    const int part = gt & 1;
    const int b    = p / HW;
    const int rem  = p - b * HW;
    const int y    = rem / WID;
    const int xw   = rem - y * WID;
    const float* xb = x + (size_t)b * 64 * HW + rem;

    // 3x3 validity bitmask (pad=1)
    unsigned vm = 0;
    #pragma unroll
    for (int ki = 0; ki < 3; ki++)
        #pragma unroll
        for (int kj = 0; kj < 3; kj++) {
            bool ok = ((unsigned)(y + ki - 1) < 56u) & ((unsigned)(xw + kj - 1) < 56u);
            vm |= (ok ? 1u : 0u) << (ki * 3 + kj);
        }

    // --- encode my 8 codebooks (cb = 8*part + c), batched gathers ---
    unsigned mine = 0;
    #pragma unroll
    for (int b2 = 0; b2 < 2; b2++) {
        float v[16];                            // 4 codebooks x 4 thresholds
        #pragma unroll
        for (int c4 = 0; c4 < 4; c4++)
            #pragma unroll
            for (int t = 0; t < 4; t++) {
                const int idx = (8 * part + 4 * b2 + c4) * 4 + t;
                v[c4 * 4 + t] =
                    ((vm >> s_kpos[idx]) & 1u) ? __ldg(xb + s_off[idx]) : 0.0f;
            }
        #pragma unroll
        for (int c4 = 0; c4 < 4; c4++) {
            const int cb = 8 * part + 4 * b2 + c4;
            int e = 0;
            #pragma unroll
            for (int t = 0; t < 4; t++) {
                const float thr = s_sval[cb * 33 + t * 8 + e];
                e = 2 * e + (v[c4 * 4 + t] >= thr ? 1 : 0);
            }
            mine |= (unsigned)e << (4 * (4 * b2 + c4));
        }
    }

    // Merge: lane^1 is the other part of this pixel. One shuffle only.
    unsigned long long codes = (unsigned long long)mine << (32 * part);
    codes |= __shfl_xor_sync(0xffffffffu, codes, 1);

    // --- accumulate, two fp16 trees (cb 0-7 / 8-15) ---
    const int rot2 = (p & 3) * 2;
    int soff[4];
    #pragma unroll
    for (int rr = 0; rr < 4; rr++)
        soff[rr] = (((2 * rr + rot2) & 7) | part) * 16;

    __half2 accA[4][4], accB[4][4];
    #pragma unroll
    for (int rr = 0; rr < 4; rr++)
        #pragma unroll
        for (int k = 0; k < 4; k++) {
            accA[rr][k] = __half2half2(__ushort_as_half(0));
            accB[rr][k] = __half2half2(__ushort_as_half(0));
        }

    #pragma unroll
    for (int cb = 0; cb < 8; cb++) {
        const int eA = (int)((codes >> (4 * cb)) & 15ull);
        const int eB = (int)((codes >> (4 * (cb + 8))) & 15ull);
        const char* rowA = s_lutb + (cb * 16 + eA) * 128;
        const char* rowB = s_lutb + ((cb + 8) * 16 + eB) * 128;
        #pragma unroll
        for (int rr = 0; rr < 4; rr++) {
            uint4 a  = *(const uint4*)(rowA + soff[rr]);
            uint4 bq = *(const uint4*)(rowB + soff[rr]);
            accA[rr][0] = __hadd2(accA[rr][0], *(__half2*)&a.x);
            accA[rr][1] = __hadd2(accA[rr][1], *(__half2*)&a.y);
            accA[rr][2] = __hadd2(accA[rr][2], *(__half2*)&a.z);
            accA[rr][3] = __hadd2(accA[rr][3], *(__half2*)&a.w);
            accB[rr][0] = __hadd2(accB[rr][0], *(__half2*)&bq.x);
            accB[rr][1] = __hadd2(accB[rr][1], *(__half2*)&bq.y);
            accB[rr][2] = __hadd2(accB[rr][2], *(__half2*)&bq.z);
            accB[rr][3] = __hadd2(accB[rr][3], *(__half2*)&bq.w);
        }
    }

    // --- fp32 merge + transpose via smem (reuse dead LUT region) ---
    // buffer: float4 s_t4[(2g+h)*66 + px], g<8, h<2, px<64 (16.9 KB)
    __syncthreads();
    float4* s_t4 = (float4*)smem_raw;
    const int pxl = tid >> 1;                  // local pixel 0..63
    #pragma unroll
    for (int rr = 0; rr < 4; rr++) {
        const int g = soff[rr] >> 4;           // channel-8 group 0..7
        float2 f0 = __half22float2(accA[rr][0]), g0 = __half22float2(accB[rr][0]);
        float2 f1 = __half22float2(accA[rr][1]), g1 = __half22float2(accB[rr][1]);
        float2 f2 = __half22float2(accA[rr][2]), g2 = __half22float2(accB[rr][2]);
        float2 f3 = __half22float2(accA[rr][3]), g3 = __half22float2(accB[rr][3]);
        float4 lo = make_float4(f0.x + g0.x, f0.y + g0.y, f1.x + g1.x, f1.y + g1.y);
        float4 hi = make_float4(f2.x + g2.x, f2.y + g2.y, f3.x + g3.x, f3.y + g3.y);
        s_t4[(2 * g + 0) * 66 + pxl] = lo;
        s_t4[(2 * g + 1) * 66 + pxl] = hi;
    }
    __syncthreads();

    // --- coalesced stores + bias: thread (gq = tid>>6, px = tid&63)
    //     stores channel groups gq*4 .. gq*4+3 for local pixel px.
    const int gq = tid >> 6;
    const int px = tid & 63;
    const int pg = blockIdx.x * 64 + px;       // global pixel
    const int bb = pg / HW;
    const int rr2 = pg - bb * HW;
    float* ob = out + (size_t)bb * 64 * HW + rr2;

    #pragma unroll
    for (int j = 0; j < 4; j++) {
        const int g = gq * 4 + j;
        float4 lo = s_t4[(2 * g + 0) * 66 + px];
        float4 hi = s_t4[(2 * g + 1) * 66 + px];
        const int ch = 8 * g;
        ob[(ch + 0) * HW] = lo.x + s_bias[ch + 0];
        ob[(ch + 1) * HW] = lo.y + s_bias[ch + 1];
        ob[(ch + 2) * HW] = lo.z + s_bias[ch + 2];
        ob[(ch + 3) * HW] = lo.w + s_bias[ch + 3];
        ob[(ch + 4) * HW] = hi.x + s_bias[ch + 4];
        ob[(ch + 5) * HW] = hi.y + s_bias[ch + 5];
        ob[(ch + 6) * HW] = hi.z + s_bias[ch + 6];
        ob[(ch + 7) * HW] = hi.w + s_bias[ch + 7];
    }
}

extern "C" void kernel_launch(void* const* d_in, const int* in_sizes, int n_in,
                              void* d_out, int out_size)
{
    const float* x    = (const float*)d_in[0];
    const int*   sidx = (const int*)  d_in[1];
    const float* sval = (const float*)d_in[2];
    const float* lut  = (const float*)d_in[3];
    const float* bias = (const float*)d_in[4];
    float* out = (float*)d_out;

    cudaFuncSetAttribute(maddness_conv2d_kernel,
                         cudaFuncAttributeMaxDynamicSharedMemorySize,
                         SMEM_BYTES);

    maddness_conv2d_kernel<<<NBLK, TPB, SMEM_BYTES>>>(x, sidx, sval, lut, bias, out);
}

// round 10
// speedup vs baseline: 1.2574x; 1.1404x over previous
#include <cuda_runtime.h>
#include <cuda_fp16.h>
#include <cstdint>

// MaddnessConv2d, round 10: R7 macro-shape (392 blocks x 128 px, 2 lanes/px,
// fp16 LUT, rotation-conflict-free LDS) + upfront MLP-32 gathers +
// stride-33 conflict-free sval walk + two-tree fp16 accumulation.
//
//   x:            (16, 64, 56, 56) f32
//   split_idxs:   (16, 4) i32
//   split_vals:   (16, 4, 8) f32
//   lookup_tables:(16, 16, 64) f32
//   bias:         (64,) f32
//   out:          (16, 64, 56, 56) f32
//
// out[p][ch] = sum_cb LUT[cb][e_cb(p)][ch] + bias[ch]. LUT in smem as fp16
// (row (cb,e) = 128B = 8 slots x 8 channels). 2 lanes/pixel: lane `part`
// reads slots s(rr) = ((2rr + 2(p&3))&7)|part -> every 8-lane LDS phase
// (4 px x 2 parts) covers all 8 bank-groups, independent of the code e.

#define NCB   16
#define HW    3136          // 56*56
#define WID   56
#define TPB   256
#define NBLK  392           // 392*256 == 2*50176 exactly; 128 pixels/block

// smem layout:
//   half  s_lut[16*16*64]    32768 B  (reused as [8][132] float4 half2 buf)
//   float s_bias[64]           256 B
//   float s_sval[16*33]       2112 B  (stride-33: conflict-free walk)
//   int   s_off[64]            256 B
//   int   s_kpos[64]           256 B
#define SM_LUT   0
#define SM_BIAS  32768
#define SM_SVAL  33024
#define SM_OFF   35136
#define SM_KPOS  35392
#define SMEM_BYTES 35648

__global__ __launch_bounds__(TPB, 3) void maddness_conv2d_kernel(
    const float* __restrict__ x,
    const int*   __restrict__ split_idxs,
    const float* __restrict__ split_vals,
    const float* __restrict__ lut,
    const float* __restrict__ bias,
    float*       __restrict__ out)
{
    extern __shared__ char smem_raw[];
    char*  s_lutb = smem_raw + SM_LUT;
    float* s_bias = (float*)(smem_raw + SM_BIAS);
    float* s_sval = (float*)(smem_raw + SM_SVAL);
    int*   s_off  = (int*)  (smem_raw + SM_OFF);
    int*   s_kpos = (int*)  (smem_raw + SM_KPOS);

    const int tid = threadIdx.x;

    // --- cooperative smem fill: LUT fp32 -> fp16, 128B rows ---
    {
        const float4* lut4 = (const float4*)lut;   // 4096 float4 (4 ch each)
        #pragma unroll
        for (int i = tid; i < 4096; i += TPB) {
            float4 lv = lut4[i];
            __half2 h0 = __floats2half2_rn(lv.x, lv.y);
            __half2 h1 = __floats2half2_rn(lv.z, lv.w);
            uint2 pk;
            pk.x = *(unsigned*)&h0;
            pk.y = *(unsigned*)&h1;
            *(uint2*)(s_lutb + (i >> 4) * 128 + (i & 15) * 8) = pk;
        }
    }
    if (tid < 64) {
        int cb = tid >> 2;                     // tid = cb*4 + t
        int si = split_idxs[tid];
        int f  = cb * 36 + si;
        int ch = f / 9;
        int r  = f - ch * 9;                   // kernel position 0..8
        int dy = r / 3 - 1;
        int dx = r - (r / 3) * 3 - 1;
        s_off[tid]  = ch * HW + dy * WID + dx;
        s_kpos[tid] = r;
        s_bias[tid] = bias[tid];
    }
    #pragma unroll
    for (int i = tid; i < NCB * 32; i += TPB)
        s_sval[(i >> 5) * 33 + (i & 31)] = split_vals[i];
    __syncthreads();

    // --- indices: 2 lanes per pixel ---
    const int gt   = blockIdx.x * TPB + tid;   // exact grid
    const int p    = gt >> 1;                  // pixel
    const int part = gt & 1;
    const int b    = p / HW;
    const int rem  = p - b * HW;
    const int y    = rem / WID;
    const int xw   = rem - y * WID;
    const float* xb = x + (size_t)b * 64 * HW + rem;

    // 3x3 validity bitmask (pad=1)
    unsigned vm = 0;
    #pragma unroll
    for (int ki = 0; ki < 3; ki++)
        #pragma unroll
        for (int kj = 0; kj < 3; kj++) {
            bool ok = ((unsigned)(y + ki - 1) < 56u) & ((unsigned)(xw + kj - 1) < 56u);
            vm |= (ok ? 1u : 0u) << (ki * 3 + kj);
        }

    // --- upfront gathers for my 8 codebooks (MLP=32; values independent of e) ---
    float v[32];
    #pragma unroll
    for (int c = 0; c < 8; c++)
        #pragma unroll
        for (int t = 0; t < 4; t++) {
            const int idx = (8 * part + c) * 4 + t;
            v[c * 4 + t] =
                ((vm >> s_kpos[idx]) & 1u) ? __ldg(xb + s_off[idx]) : 0.0f;
        }

    // --- threshold walk (conflict-free sval: bank = cb + 8t + e) ---
    unsigned mine = 0;
    #pragma unroll
    for (int c = 0; c < 8; c++) {
        const int cb = 8 * part + c;
        int e = 0;
        #pragma unroll
        for (int t = 0; t < 4; t++) {
            const float thr = s_sval[cb * 33 + t * 8 + e];
            e = 2 * e + (v[c * 4 + t] >= thr ? 1 : 0);
        }
        mine |= (unsigned)e << (4 * c);
    }

    // Merge: lane^1 is the other part of this pixel. One shuffle only.
    unsigned long long codes = (unsigned long long)mine << (32 * part);
    codes |= __shfl_xor_sync(0xffffffffu, codes, 1);

    // --- accumulate, two fp16 trees (cb 0-7 / 8-15) ---
    const int rot2 = (p & 3) * 2;
    int soff[4];
    #pragma unroll
    for (int rr = 0; rr < 4; rr++)
        soff[rr] = (((2 * rr + rot2) & 7) | part) * 16;

    __half2 accA[4][4], accB[4][4];
    #pragma unroll
    for (int rr = 0; rr < 4; rr++)
        #pragma unroll
        for (int k = 0; k < 4; k++) {
            accA[rr][k] = __half2half2(__ushort_as_half(0));
            accB[rr][k] = __half2half2(__ushort_as_half(0));
        }

    #pragma unroll
    for (int cb = 0; cb < 8; cb++) {
        const int eA = (int)((codes >> (4 * cb)) & 15ull);
        const int eB = (int)((codes >> (4 * (cb + 8))) & 15ull);
        const char* rowA = s_lutb + (cb * 16 + eA) * 128;
        const char* rowB = s_lutb + ((cb + 8) * 16 + eB) * 128;
        #pragma unroll
        for (int rr = 0; rr < 4; rr++) {
            uint4 a  = *(const uint4*)(rowA + soff[rr]);
            uint4 bq = *(const uint4*)(rowB + soff[rr]);
            accA[rr][0] = __hadd2(accA[rr][0], *(__half2*)&a.x);
            accA[rr][1] = __hadd2(accA[rr][1], *(__half2*)&a.y);
            accA[rr][2] = __hadd2(accA[rr][2], *(__half2*)&a.z);
            accA[rr][3] = __hadd2(accA[rr][3], *(__half2*)&a.w);
            accB[rr][0] = __hadd2(accB[rr][0], *(__half2*)&bq.x);
            accB[rr][1] = __hadd2(accB[rr][1], *(__half2*)&bq.y);
            accB[rr][2] = __hadd2(accB[rr][2], *(__half2*)&bq.z);
            accB[rr][3] = __hadd2(accB[rr][3], *(__half2*)&bq.w);
        }
    }

    // --- fp16 tree merge + transpose via smem (reuse dead LUT region) ---
    // buffer: float4 s_buf[g*132 + px] of packed half2, g<8, px<128 (16.9 KB)
    __syncthreads();
    float4* s_buf = (float4*)smem_raw;
    const int pxl = tid >> 1;                  // local pixel 0..127
    #pragma unroll
    for (int rr = 0; rr < 4; rr++) {
        const int g = soff[rr] >> 4;           // channel-8 group 0..7
        __half2 m0 = __hadd2(accA[rr][0], accB[rr][0]);
        __half2 m1 = __hadd2(accA[rr][1], accB[rr][1]);
        __half2 m2 = __hadd2(accA[rr][2], accB[rr][2]);
        __half2 m3 = __hadd2(accA[rr][3], accB[rr][3]);
        float4 pk;
        pk.x = *(float*)&m0;
        pk.y = *(float*)&m1;
        pk.z = *(float*)&m2;
        pk.w = *(float*)&m3;
        s_buf[g * 132 + pxl] = pk;
    }
    __syncthreads();

    // --- coalesced stores with fp32 finalize + bias ---
    // thread (q2 = tid>>7, pq = tid&127) stores groups q2*4 .. q2*4+3.
    const int q2 = tid >> 7;
    const int pq = tid & 127;
    const int pg = blockIdx.x * 128 + pq;      // global pixel
    const int bb = pg / HW;
    const int rr2 = pg - bb * HW;
    float* ob = out + (size_t)bb * 64 * HW + rr2;

    #pragma unroll
    for (int j = 0; j < 4; j++) {
        const int g = q2 * 4 + j;
        float4 pk = s_buf[g * 132 + pq];
        float2 f0 = __half22float2(*(__half2*)&pk.x);
        float2 f1 = __half22float2(*(__half2*)&pk.y);
        float2 f2 = __half22float2(*(__half2*)&pk.z);
        float2 f3 = __half22float2(*(__half2*)&pk.w);
        const int ch = 8 * g;
        ob[(ch + 0) * HW] = f0.x + s_bias[ch + 0];
        ob[(ch + 1) * HW] = f0.y + s_bias[ch + 1];
        ob[(ch + 2) * HW] = f1.x + s_bias[ch + 2];
        ob[(ch + 3) * HW] = f1.y + s_bias[ch + 3];
        ob[(ch + 4) * HW] = f2.x + s_bias[ch + 4];
        ob[(ch + 5) * HW] = f2.y + s_bias[ch + 5];
        ob[(ch + 6) * HW] = f3.x + s_bias[ch + 6];
        ob[(ch + 7) * HW] = f3.y + s_bias[ch + 7];
    }
}

extern "C" void kernel_launch(void* const* d_in, const int* in_sizes, int n_in,
                              void* d_out, int out_size)
{
    const float* x    = (const float*)d_in[0];
    const int*   sidx = (const int*)  d_in[1];
    const float* sval = (const float*)d_in[2];
    const float* lut  = (const float*)d_in[3];
    const float* bias = (const float*)d_in[4];
    float* out = (float*)d_out;

    cudaFuncSetAttribute(maddness_conv2d_kernel,
                         cudaFuncAttributeMaxDynamicSharedMemorySize,
                         SMEM_BYTES);

    maddness_conv2d_kernel<<<NBLK, TPB, SMEM_BYTES>>>(x, sidx, sval, lut, bias, out);
}